// round 14
// baseline (speedup 1.0000x reference)
#include <cuda_runtime.h>
#include <cuda_fp16.h>
#include <cstdint>
#include <cmath>

#define BB 64
#define SS 1024
#define DD 768

// ---------------------------------------------------------------------------
// Scratch (__device__ globals; no cudaMalloc allowed)
// ---------------------------------------------------------------------------
__device__ __half g_Hhi[(size_t)BB * SS * DD];   // 96 MB
__device__ __half g_Phi[(size_t)BB * SS * DD];   // 96 MB
__device__ __half g_Mhi[DD * DD];
__device__ float  g_q[BB * SS];

// ---------------------------------------------------------------------------
// Helpers (baseline PTX only: cp.async / ldmatrix / mma.sync — no 'a' features)
// ---------------------------------------------------------------------------
__device__ __forceinline__ uint32_t smem_u32(const void* p) {
    return (uint32_t)__cvta_generic_to_shared(p);
}

__device__ __forceinline__ void cpasync16(uint32_t s, const void* g) {
    asm volatile("cp.async.cg.shared.global [%0], [%1], 16;" :: "r"(s), "l"(g) : "memory");
}

__device__ __forceinline__ void ldm4(uint32_t& r0, uint32_t& r1, uint32_t& r2, uint32_t& r3,
                                     uint32_t a) {
    asm volatile("ldmatrix.sync.aligned.m8n8.x4.shared.b16 {%0,%1,%2,%3}, [%4];"
                 : "=r"(r0), "=r"(r1), "=r"(r2), "=r"(r3) : "r"(a));
}

__device__ __forceinline__ void mma16816(float* d, const uint32_t* a, const uint32_t* b) {
    asm volatile("mma.sync.aligned.m16n8k16.row.col.f32.f16.f16.f32 "
                 "{%0,%1,%2,%3}, {%4,%5,%6,%7}, {%8,%9}, {%0,%1,%2,%3};"
                 : "+f"(d[0]), "+f"(d[1]), "+f"(d[2]), "+f"(d[3])
                 : "r"(a[0]), "r"(a[1]), "r"(a[2]), "r"(a[3]), "r"(b[0]), "r"(b[1]));
}

// ---------------------------------------------------------------------------
// Merged conversion kernel: blocks [0, NB_CONV) convert batch -> Hhi (fp16),
// tail blocks build Mh = fl16(proj + proj^T) and zero g_q.
// ---------------------------------------------------------------------------
#define NB_CONV ((int)(((size_t)BB * SS * DD / 4) / 256))   // 49152
#define NB_PREP ((DD * DD + 255) / 256)                     // 2304

__global__ void k_conv(const float* __restrict__ batch, const float* __restrict__ proj) {
    if (blockIdx.x < NB_CONV) {
        size_t i = ((size_t)blockIdx.x * 256 + threadIdx.x) * 4;
        float4 v = *(const float4*)(batch + i);
        __half2 a, b;
        a.x = __float2half_rn(v.x); a.y = __float2half_rn(v.y);
        b.x = __float2half_rn(v.z); b.y = __float2half_rn(v.w);
        ((__half2*)(g_Hhi + i))[0] = a;
        ((__half2*)(g_Hhi + i))[1] = b;
    } else {
        int idx = (blockIdx.x - NB_CONV) * 256 + threadIdx.x;
        if (idx < DD * DD) {
            int i = idx / DD, j = idx % DD;
            g_Mhi[idx] = __float2half_rn(proj[idx] + proj[j * DD + i]);
        }
        if (idx < BB * SS) g_q[idx] = 0.0f;   // zero q accumulator each launch
    }
}

// ---------------------------------------------------------------------------
// Single-term fp16 NT GEMM via mma.sync (HMMA.16816 f16):
//   EPI=false : D = Hhi.Mh^T  -> writes Phi (fp16) AND accumulates
//               q[b,i] = 0.5 * P_i . h_i via atomicAdd (fp32 acc).
//   EPI=true  : D = Phi.Hhi^T; triangular block grid (bi >= bj),
//               mirrored via smem transpose.
// 128 threads, 2x2 warp grid, 64x64 warp tiles: 8 ldm4 per 32 MMAs
// (0.25 KB/MMA vs 0.375 before) -> smem crossbar no longer co-binds.
// launch_bounds(128,3): 3 CTAs/SM (regs<=168, smem 3x67.6KB = 203KB).
// ---------------------------------------------------------------------------
#define BM 128
#define BN 128
#define BK 32
#define NSTAGE 4
#define TILE_BYTES 8192                      // 128 rows x 64B
#define STAGE_B (2 * TILE_BYTES)
#define KITERS (DD / BK)                     // 24
#define TPAD 132
#define SMEM_MM (128 * TPAD * 4)             // 67584 >= NSTAGE*STAGE_B = 65536

// smem tile layout: row r (64B), chunk c (16B, 0..3), swizzle c ^= (r>>1)&3
// 128 threads: 4 iterations of 128 cp.async cover 8KB.
__device__ __forceinline__ void load_tile(uint32_t s, const __half* g, int kt, int tid) {
    #pragma unroll
    for (int i = 0; i < 4; i++) {
        int id = tid + i * 128;                 // 0..511
        int r  = id >> 2;                       // 0..127
        int c  = id & 3;                        // 0..3
        const char* gp = (const char*)g + (size_t)r * (DD * 2) + (size_t)kt * 64 + c * 16;
        uint32_t sa = s + r * 64 + ((c ^ ((r >> 1) & 3)) << 4);
        cpasync16(sa, gp);
    }
}

template <bool EPI>
__global__ void __launch_bounds__(128, 3) k_mm(float* __restrict__ out,
                                               const float* __restrict__ batch) {
    extern __shared__ char smem[];
    const uint32_t sb = smem_u32(smem);

    const int tid = threadIdx.x, lane = tid & 31, wid = tid >> 5;
    const int wm = wid & 1;        // warp M index (0..1), tile 64 rows
    const int wn = wid >> 1;       // warp N index (0..1), tile 64 cols
    const int b = blockIdx.z;

    int rowA0, rowB0, bi = 0, bj = 0;
    if (EPI) {
        int t = blockIdx.x;                      // 0..35 lower-triangular index
        bi = (int)((sqrtf(8.f * t + 1.f) - 1.f) * 0.5f);
        while ((bi + 1) * (bi + 2) / 2 <= t) bi++;
        while (bi * (bi + 1) / 2 > t) bi--;
        bj = t - bi * (bi + 1) / 2;
        rowA0 = bi * BM;
        rowB0 = bj * BN;
    } else {
        rowA0 = blockIdx.y * BM;
        rowB0 = blockIdx.x * BN;
    }

    const __half *pA, *pB;
    if (EPI) {
        pA = g_Phi + (size_t)b * SS * DD + (size_t)rowA0 * DD;
        pB = g_Hhi + (size_t)b * SS * DD + (size_t)rowB0 * DD;
    } else {
        pA = g_Hhi + (size_t)b * SS * DD + (size_t)rowA0 * DD;
        pB = g_Mhi + (size_t)rowB0 * DD;        // M symmetric: row j == col j
    }

    // ldmatrix per-lane addressing
    const int g8 = lane >> 3, r8 = lane & 7;
    uint32_t aRB[4];  int aSW[4];
    #pragma unroll
    for (int i = 0; i < 4; i++) {
        int r = wm * 64 + i * 16 + r8 + (g8 & 1) * 8;
        aRB[i] = (uint32_t)r * 64;
        aSW[i] = (r >> 1) & 3;
    }
    const int aCB = g8 >> 1;
    uint32_t bRB[4];  int bSW[4];
    #pragma unroll
    for (int j = 0; j < 4; j++) {
        int r = wn * 64 + j * 16 + r8 + (g8 >> 1) * 8;
        bRB[j] = (uint32_t)r * 64;
        bSW[j] = (r >> 1) & 3;
    }
    const int bCB = g8 & 1;

    float acc[4][8][4] = {};     // i (16-row), jj (8-col), frag

    // Prologue: stages 0..NSTAGE-2
    #pragma unroll
    for (int s = 0; s < NSTAGE - 1; s++) {
        uint32_t st = sb + (uint32_t)s * STAGE_B;
        load_tile(st,              pA, s, tid);
        load_tile(st + TILE_BYTES, pB, s, tid);
        asm volatile("cp.async.commit_group;" ::: "memory");
    }

    #pragma unroll 1
    for (int kt = 0; kt < KITERS; kt++) {
        if (kt < KITERS - 2)       asm volatile("cp.async.wait_group 2;" ::: "memory");
        else if (kt == KITERS - 2) asm volatile("cp.async.wait_group 1;" ::: "memory");
        else                       asm volatile("cp.async.wait_group 0;" ::: "memory");
        __syncthreads();

        // Prefetch stage kt+3 (overwrites stage used by kt-1; safe after barrier)
        if (kt + NSTAGE - 1 < KITERS) {
            uint32_t st = sb + (uint32_t)((kt + NSTAGE - 1) % NSTAGE) * STAGE_B;
            int kn = kt + NSTAGE - 1;
            load_tile(st,              pA, kn, tid);
            load_tile(st + TILE_BYTES, pB, kn, tid);
            asm volatile("cp.async.commit_group;" ::: "memory");
        }

        const uint32_t st = sb + (uint32_t)(kt % NSTAGE) * STAGE_B;
        #pragma unroll
        for (int ks = 0; ks < 2; ks++) {
            uint32_t ah[4][4], bh[2][4];
            #pragma unroll
            for (int i = 0; i < 4; i++) {
                uint32_t off = aRB[i] + (uint32_t)(((aCB + ks * 2) ^ aSW[i]) << 4);
                ldm4(ah[i][0], ah[i][1], ah[i][2], ah[i][3], st + off);
            }
            // B halves JIT-loaded to keep live regs under the 168 cap
            #pragma unroll
            for (int jh = 0; jh < 2; jh++) {
                #pragma unroll
                for (int j = 0; j < 2; j++) {
                    int jb = jh * 2 + j;
                    uint32_t off = bRB[jb] + (uint32_t)(((bCB + ks * 2) ^ bSW[jb]) << 4);
                    ldm4(bh[j][0], bh[j][1], bh[j][2], bh[j][3], st + TILE_BYTES + off);
                }
                #pragma unroll
                for (int i = 0; i < 4; i++)
                    #pragma unroll
                    for (int jj = 0; jj < 4; jj++)
                        mma16816(acc[i][jh * 4 + jj], ah[i], &bh[jj >> 1][(jj & 1) * 2]);
            }
        }
    }

    // ------------------------------ Epilogue -------------------------------
    const int mrow = rowA0 + wm * 64 + lane / 4;       // +i*16, +8
    const int ncol = rowB0 + wn * 64 + (lane % 4) * 2; // +jj*8

    if (!EPI) {
        __half* dh = g_Phi + (size_t)b * SS * DD;
        const float* Hb = batch + (size_t)b * SS * DD;
        #pragma unroll
        for (int i = 0; i < 4; i++)
            #pragma unroll
            for (int jj = 0; jj < 8; jj++) {
                int r0 = mrow + i * 16, c = ncol + jj * 8;
                #pragma unroll
                for (int h = 0; h < 2; h++) {
                    int r = r0 + h * 8;
                    __half2 hh;
                    hh.x = __float2half_rn(acc[i][jj][2 * h + 0]);
                    hh.y = __float2half_rn(acc[i][jj][2 * h + 1]);
                    *(__half2*)(dh + (size_t)r * DD + c) = hh;
                }
            }
        // Fused q: q[b,r] += 0.5 * sum_c P[r,c] * H[r,c] over this warp's 64 cols
        #pragma unroll
        for (int i = 0; i < 4; i++)
            #pragma unroll
            for (int h = 0; h < 2; h++) {
                int r = mrow + i * 16 + h * 8;
                float p = 0.f;
                #pragma unroll
                for (int jj = 0; jj < 8; jj++) {
                    int c = ncol + jj * 8;
                    float2 hv = *(const float2*)(Hb + (size_t)r * DD + c);
                    p += acc[i][jj][2 * h + 0] * hv.x + acc[i][jj][2 * h + 1] * hv.y;
                }
                p += __shfl_xor_sync(0xFFFFFFFFu, p, 1);
                p += __shfl_xor_sync(0xFFFFFFFFu, p, 2);
                if ((lane & 3) == 0)
                    atomicAdd(&g_q[(size_t)b * SS + r], 0.5f * p);
            }
    } else {
        const float* qb = g_q + (size_t)b * SS;
        float* ob = out + (size_t)b * SS * SS;

        // Fold q_i + q_j - acc into acc
        #pragma unroll
        for (int i = 0; i < 4; i++) {
            float qi0 = qb[mrow + i * 16];
            float qi1 = qb[mrow + i * 16 + 8];
            #pragma unroll
            for (int jj = 0; jj < 8; jj++) {
                int c = ncol + jj * 8;
                float qj0 = qb[c], qj1 = qb[c + 1];
                acc[i][jj][0] = qi0 + qj0 - acc[i][jj][0];
                acc[i][jj][1] = qi0 + qj1 - acc[i][jj][1];
                acc[i][jj][2] = qi1 + qj0 - acc[i][jj][2];
                acc[i][jj][3] = qi1 + qj1 - acc[i][jj][3];
            }
        }

        const bool mirror = (bi != bj);
        float* sm = (float*)smem;
        if (mirror) {
            __syncthreads();   // all warps done reading pipeline stages
            // Stash transposed: sm[c_local * TPAD + r_local]  (conflict-free)
            int rl = wm * 64 + lane / 4;
            int cl = wn * 64 + (lane % 4) * 2;
            #pragma unroll
            for (int i = 0; i < 4; i++)
                #pragma unroll
                for (int jj = 0; jj < 8; jj++) {
                    int r0 = rl + i * 16, c = cl + jj * 8;
                    sm[(c    ) * TPAD + r0    ] = acc[i][jj][0];
                    sm[(c + 1) * TPAD + r0    ] = acc[i][jj][1];
                    sm[(c    ) * TPAD + r0 + 8] = acc[i][jj][2];
                    sm[(c + 1) * TPAD + r0 + 8] = acc[i][jj][3];
                }
        }

        // Direct write of block (bi, bj)
        #pragma unroll
        for (int i = 0; i < 4; i++)
            #pragma unroll
            for (int jj = 0; jj < 8; jj++) {
                int c = ncol + jj * 8;
                *(float2*)(ob + (size_t)(mrow + i * 16)     * SS + c) =
                    make_float2(acc[i][jj][0], acc[i][jj][1]);
                *(float2*)(ob + (size_t)(mrow + i * 16 + 8) * SS + c) =
                    make_float2(acc[i][jj][2], acc[i][jj][3]);
            }

        if (mirror) {
            __syncthreads();
            // Coalesced write of transposed block to (bj, bi)
            #pragma unroll
            for (int it = 0; it < 32; it++) {
                int idx = tid + it * 128;       // 0..4095
                int tr  = idx >> 5;             // 0..127 (row of mirrored block)
                int f4  = idx & 31;             // float4 index
                float4 v = *(float4*)&sm[tr * TPAD + f4 * 4];
                *(float4*)(ob + (size_t)(rowB0 + tr) * SS + rowA0 + f4 * 4) = v;
            }
        }
    }
}

// ---------------------------------------------------------------------------
extern "C" void kernel_launch(void* const* d_in, const int* in_sizes, int n_in,
                              void* d_out, int out_size) {
    const float* batch = (const float*)d_in[0];   // (64, 1024, 768) fp32
    const float* proj  = (const float*)d_in[1];   // (768, 768) fp32
    float* out = (float*)d_out;                   // (64, 1024, 1024) fp32

    cudaFuncSetAttribute(k_mm<false>, cudaFuncAttributeMaxDynamicSharedMemorySize, SMEM_MM);
    cudaFuncSetAttribute(k_mm<true>,  cudaFuncAttributeMaxDynamicSharedMemorySize, SMEM_MM);

    k_conv<<<NB_CONV + NB_PREP, 256>>>(batch, proj);                          // (1)
    k_mm<false><<<dim3(DD / BN, SS / BM, BB), 128, SMEM_MM>>>(out, batch);    // (2) P=H*Mh + q
    k_mm<true><<<dim3(36, 1, BB), 128, SMEM_MM>>>(out, batch);                // (3) dists
}

// round 16
// speedup vs baseline: 1.0917x; 1.0917x over previous
#include <cuda_runtime.h>
#include <cuda_fp16.h>
#include <cstdint>
#include <cmath>

#define BB 64
#define SS 1024
#define DD 768

// ---------------------------------------------------------------------------
// Scratch (__device__ globals; no cudaMalloc allowed)
// ---------------------------------------------------------------------------
__device__ __half g_Hhi[(size_t)BB * SS * DD];   // 96 MB
__device__ __half g_Phi[(size_t)BB * SS * DD];   // 96 MB
__device__ __half g_Mhi[DD * DD];
__device__ float  g_q[BB * SS];

// ---------------------------------------------------------------------------
// Helpers (baseline PTX only: cp.async / ldmatrix / mma.sync — no 'a' features)
// ---------------------------------------------------------------------------
__device__ __forceinline__ uint32_t smem_u32(const void* p) {
    return (uint32_t)__cvta_generic_to_shared(p);
}

__device__ __forceinline__ void cpasync16(uint32_t s, const void* g) {
    asm volatile("cp.async.cg.shared.global [%0], [%1], 16;" :: "r"(s), "l"(g) : "memory");
}

__device__ __forceinline__ void ldm4(uint32_t& r0, uint32_t& r1, uint32_t& r2, uint32_t& r3,
                                     uint32_t a) {
    asm volatile("ldmatrix.sync.aligned.m8n8.x4.shared.b16 {%0,%1,%2,%3}, [%4];"
                 : "=r"(r0), "=r"(r1), "=r"(r2), "=r"(r3) : "r"(a));
}

__device__ __forceinline__ void mma16816(float* d, const uint32_t* a, const uint32_t* b) {
    asm volatile("mma.sync.aligned.m16n8k16.row.col.f32.f16.f16.f32 "
                 "{%0,%1,%2,%3}, {%4,%5,%6,%7}, {%8,%9}, {%0,%1,%2,%3};"
                 : "+f"(d[0]), "+f"(d[1]), "+f"(d[2]), "+f"(d[3])
                 : "r"(a[0]), "r"(a[1]), "r"(a[2]), "r"(a[3]), "r"(b[0]), "r"(b[1]));
}

// ---------------------------------------------------------------------------
// Merged conversion kernel: blocks [0, NB_CONV) convert batch -> Hhi (fp16),
// tail blocks build Mh = fl16(proj + proj^T) and zero g_q.
// ---------------------------------------------------------------------------
#define NB_CONV ((int)(((size_t)BB * SS * DD / 4) / 256))   // 49152
#define NB_PREP ((DD * DD + 255) / 256)                     // 2304

__global__ void k_conv(const float* __restrict__ batch, const float* __restrict__ proj) {
    if (blockIdx.x < NB_CONV) {
        size_t i = ((size_t)blockIdx.x * 256 + threadIdx.x) * 4;
        float4 v = *(const float4*)(batch + i);
        __half2 a, b;
        a.x = __float2half_rn(v.x); a.y = __float2half_rn(v.y);
        b.x = __float2half_rn(v.z); b.y = __float2half_rn(v.w);
        ((__half2*)(g_Hhi + i))[0] = a;
        ((__half2*)(g_Hhi + i))[1] = b;
    } else {
        int idx = (blockIdx.x - NB_CONV) * 256 + threadIdx.x;
        if (idx < DD * DD) {
            int i = idx / DD, j = idx % DD;
            g_Mhi[idx] = __float2half_rn(proj[idx] + proj[j * DD + i]);
        }
        if (idx < BB * SS) g_q[idx] = 0.0f;   // zero q accumulator each launch
    }
}

// ---------------------------------------------------------------------------
// Single-term fp16 NT GEMM via mma.sync (HMMA.16816 f16):
//   EPI=false : D = Hhi.Mh^T  -> writes Phi (fp16) AND accumulates
//               q[b,i] = 0.5 * P_i . h_i via atomicAdd (fp32 acc).
//   EPI=true  : D = Phi.Hhi^T; triangular block grid (bi >= bj),
//               mirrored via smem transpose.
// R13 shape (256 thr, 2x4 warp grid, 64x32 warp tiles, 16 warps/SM) but
// BK=64 (128B rows, full SW128 swizzle): k-loop 24 -> 12 iterations, halving
// barrier/wait_group convoy overhead. NSTAGE=3 -> 96KB, 2 CTAs/SM.
// ---------------------------------------------------------------------------
#define BM 128
#define BN 128
#define BK 64
#define NSTAGE 3
#define TILE_BYTES 16384                     // 128 rows x 128B
#define STAGE_B (2 * TILE_BYTES)             // 32768
#define KITERS (DD / BK)                     // 12
#define TPAD 132
#define SMEM_MM (NSTAGE * STAGE_B)           // 98304 (>= 128*TPAD*4 = 67584)

// smem tile layout: row r (128B), chunk c (16B, 0..7), swizzle c ^= r&7
__device__ __forceinline__ void load_tile(uint32_t s, const __half* g, int kt, int tid) {
    #pragma unroll
    for (int i = 0; i < 4; i++) {
        int id = tid + i * 256;                 // 0..1023
        int r  = id >> 3;                       // 0..127
        int c  = id & 7;                        // 0..7
        const char* gp = (const char*)g + (size_t)r * (DD * 2) + (size_t)kt * 128 + c * 16;
        uint32_t sa = s + r * 128 + ((c ^ (r & 7)) << 4);
        cpasync16(sa, gp);
    }
}

template <bool EPI>
__global__ void __launch_bounds__(256, 2) k_mm(float* __restrict__ out,
                                               const float* __restrict__ batch) {
    extern __shared__ char smem[];
    const uint32_t sb = smem_u32(smem);

    const int tid = threadIdx.x, lane = tid & 31, wid = tid >> 5;
    const int wm = wid & 1;        // warp M index (0..1), tile 64 rows
    const int wn = wid >> 1;       // warp N index (0..3), tile 32 cols
    const int b = blockIdx.z;

    int rowA0, rowB0, bi = 0, bj = 0;
    if (EPI) {
        int t = blockIdx.x;                      // 0..35 lower-triangular index
        bi = (int)((sqrtf(8.f * t + 1.f) - 1.f) * 0.5f);
        while ((bi + 1) * (bi + 2) / 2 <= t) bi++;
        while (bi * (bi + 1) / 2 > t) bi--;
        bj = t - bi * (bi + 1) / 2;
        rowA0 = bi * BM;
        rowB0 = bj * BN;
    } else {
        rowA0 = blockIdx.y * BM;
        rowB0 = blockIdx.x * BN;
    }

    const __half *pA, *pB;
    if (EPI) {
        pA = g_Phi + (size_t)b * SS * DD + (size_t)rowA0 * DD;
        pB = g_Hhi + (size_t)b * SS * DD + (size_t)rowB0 * DD;
    } else {
        pA = g_Hhi + (size_t)b * SS * DD + (size_t)rowA0 * DD;
        pB = g_Mhi + (size_t)rowB0 * DD;        // M symmetric: row j == col j
    }

    // ldmatrix per-lane addressing (128B rows, swizzle = r&7)
    const int g8 = lane >> 3, r8 = lane & 7;
    uint32_t aRB[4];  int aSW[4];
    #pragma unroll
    for (int i = 0; i < 4; i++) {
        int r = wm * 64 + i * 16 + r8 + (g8 & 1) * 8;
        aRB[i] = (uint32_t)r * 128;
        aSW[i] = r & 7;
    }
    const int aCB = g8 >> 1;
    uint32_t bRB[2];  int bSW[2];
    #pragma unroll
    for (int j = 0; j < 2; j++) {
        int r = wn * 32 + j * 16 + r8 + (g8 >> 1) * 8;
        bRB[j] = (uint32_t)r * 128;
        bSW[j] = r & 7;
    }
    const int bCB = g8 & 1;

    float acc[4][4][4] = {};

    // Prologue: stages 0..NSTAGE-2
    #pragma unroll
    for (int s = 0; s < NSTAGE - 1; s++) {
        uint32_t st = sb + (uint32_t)s * STAGE_B;
        load_tile(st,              pA, s, tid);
        load_tile(st + TILE_BYTES, pB, s, tid);
        asm volatile("cp.async.commit_group;" ::: "memory");
    }

    #pragma unroll 1
    for (int kt = 0; kt < KITERS; kt++) {
        if (kt < KITERS - 1) asm volatile("cp.async.wait_group 1;" ::: "memory");
        else                 asm volatile("cp.async.wait_group 0;" ::: "memory");
        __syncthreads();

        // Prefetch stage kt+2 (overwrites stage used by kt-1; safe after barrier)
        if (kt + NSTAGE - 1 < KITERS) {
            uint32_t st = sb + (uint32_t)((kt + NSTAGE - 1) % NSTAGE) * STAGE_B;
            int kn = kt + NSTAGE - 1;
            load_tile(st,              pA, kn, tid);
            load_tile(st + TILE_BYTES, pB, kn, tid);
            asm volatile("cp.async.commit_group;" ::: "memory");
        }

        const uint32_t st = sb + (uint32_t)(kt % NSTAGE) * STAGE_B;
        #pragma unroll
        for (int ks = 0; ks < 4; ks++) {
            uint32_t ah[4][4], bh[2][4];
            #pragma unroll
            for (int i = 0; i < 4; i++) {
                uint32_t off = aRB[i] + (uint32_t)(((aCB + ks * 2) ^ aSW[i]) << 4);
                ldm4(ah[i][0], ah[i][1], ah[i][2], ah[i][3], st + off);
            }
            #pragma unroll
            for (int j = 0; j < 2; j++) {
                uint32_t off = bRB[j] + (uint32_t)(((bCB + ks * 2) ^ bSW[j]) << 4);
                ldm4(bh[j][0], bh[j][1], bh[j][2], bh[j][3], st + TILE_BYTES + off);
            }
            #pragma unroll
            for (int i = 0; i < 4; i++)
                #pragma unroll
                for (int j = 0; j < 4; j++)
                    mma16816(acc[i][j], ah[i], &bh[j >> 1][(j & 1) * 2]);
        }
    }

    // ------------------------------ Epilogue -------------------------------
    const int mrow = rowA0 + wm * 64 + lane / 4;       // +i*16, +8
    const int ncol = rowB0 + wn * 32 + (lane % 4) * 2; // +j*8

    if (!EPI) {
        __half* dh = g_Phi + (size_t)b * SS * DD;
        const float* Hb = batch + (size_t)b * SS * DD;
        #pragma unroll
        for (int i = 0; i < 4; i++)
            #pragma unroll
            for (int j = 0; j < 4; j++) {
                int r0 = mrow + i * 16, c = ncol + j * 8;
                #pragma unroll
                for (int h = 0; h < 2; h++) {
                    int r = r0 + h * 8;
                    __half2 hh;
                    hh.x = __float2half_rn(acc[i][j][2 * h + 0]);
                    hh.y = __float2half_rn(acc[i][j][2 * h + 1]);
                    *(__half2*)(dh + (size_t)r * DD + c) = hh;
                }
            }
        // Fused q: q[b,r] += 0.5 * sum_c P[r,c] * H[r,c] over this 128-col panel
        #pragma unroll
        for (int i = 0; i < 4; i++)
            #pragma unroll
            for (int h = 0; h < 2; h++) {
                int r = mrow + i * 16 + h * 8;
                float p = 0.f;
                #pragma unroll
                for (int j = 0; j < 4; j++) {
                    int c = ncol + j * 8;
                    float2 hv = *(const float2*)(Hb + (size_t)r * DD + c);
                    p += acc[i][j][2 * h + 0] * hv.x + acc[i][j][2 * h + 1] * hv.y;
                }
                p += __shfl_xor_sync(0xFFFFFFFFu, p, 1);
                p += __shfl_xor_sync(0xFFFFFFFFu, p, 2);
                if ((lane & 3) == 0)
                    atomicAdd(&g_q[(size_t)b * SS + r], 0.5f * p);
            }
    } else {
        const float* qb = g_q + (size_t)b * SS;
        float* ob = out + (size_t)b * SS * SS;

        // Fold q_i + q_j - acc into acc
        #pragma unroll
        for (int i = 0; i < 4; i++) {
            float qi0 = qb[mrow + i * 16];
            float qi1 = qb[mrow + i * 16 + 8];
            #pragma unroll
            for (int j = 0; j < 4; j++) {
                int c = ncol + j * 8;
                float qj0 = qb[c], qj1 = qb[c + 1];
                acc[i][j][0] = qi0 + qj0 - acc[i][j][0];
                acc[i][j][1] = qi0 + qj1 - acc[i][j][1];
                acc[i][j][2] = qi1 + qj0 - acc[i][j][2];
                acc[i][j][3] = qi1 + qj1 - acc[i][j][3];
            }
        }

        const bool mirror = (bi != bj);
        float* sm = (float*)smem;
        if (mirror) {
            __syncthreads();   // all warps done reading pipeline stages
            // Stash transposed: sm[c_local * TPAD + r_local]  (conflict-free)
            int rl = wm * 64 + lane / 4;
            int cl = wn * 32 + (lane % 4) * 2;
            #pragma unroll
            for (int i = 0; i < 4; i++)
                #pragma unroll
                for (int j = 0; j < 4; j++) {
                    int r0 = rl + i * 16, c = cl + j * 8;
                    sm[(c    ) * TPAD + r0    ] = acc[i][j][0];
                    sm[(c + 1) * TPAD + r0    ] = acc[i][j][1];
                    sm[(c    ) * TPAD + r0 + 8] = acc[i][j][2];
                    sm[(c + 1) * TPAD + r0 + 8] = acc[i][j][3];
                }
        }

        // Direct write of block (bi, bj)
        #pragma unroll
        for (int i = 0; i < 4; i++)
            #pragma unroll
            for (int j = 0; j < 4; j++) {
                int c = ncol + j * 8;
                *(float2*)(ob + (size_t)(mrow + i * 16)     * SS + c) =
                    make_float2(acc[i][j][0], acc[i][j][1]);
                *(float2*)(ob + (size_t)(mrow + i * 16 + 8) * SS + c) =
                    make_float2(acc[i][j][2], acc[i][j][3]);
            }

        if (mirror) {
            __syncthreads();
            // Coalesced write of transposed block to (bj, bi)
            #pragma unroll
            for (int it = 0; it < 16; it++) {
                int idx = tid + it * 256;       // 0..4095
                int tr  = idx >> 5;             // 0..127 (row of mirrored block)
                int f4  = idx & 31;             // float4 index
                float4 v = *(float4*)&sm[tr * TPAD + f4 * 4];
                *(float4*)(ob + (size_t)(rowB0 + tr) * SS + rowA0 + f4 * 4) = v;
            }
        }
    }
}

// ---------------------------------------------------------------------------
extern "C" void kernel_launch(void* const* d_in, const int* in_sizes, int n_in,
                              void* d_out, int out_size) {
    const float* batch = (const float*)d_in[0];   // (64, 1024, 768) fp32
    const float* proj  = (const float*)d_in[1];   // (768, 768) fp32
    float* out = (float*)d_out;                   // (64, 1024, 1024) fp32

    cudaFuncSetAttribute(k_mm<false>, cudaFuncAttributeMaxDynamicSharedMemorySize, SMEM_MM);
    cudaFuncSetAttribute(k_mm<true>,  cudaFuncAttributeMaxDynamicSharedMemorySize, SMEM_MM);

    k_conv<<<NB_CONV + NB_PREP, 256>>>(batch, proj);                          // (1)
    k_mm<false><<<dim3(DD / BN, SS / BM, BB), 256, SMEM_MM>>>(out, batch);    // (2) P=H*Mh + q
    k_mm<true><<<dim3(36, 1, BB), 256, SMEM_MM>>>(out, batch);                // (3) dists
}